// round 13
// baseline (speedup 1.0000x reference)
#include <cuda_runtime.h>
#include <math.h>
#include <stdint.h>
#include <mma.h>

using namespace nvcuda;

#define LL 512
#define BB 64
#define EE 256
#define HH 256
#define HID 512
#define NG 1024      // 4*H gate rows
#define MM 32768     // LL*BB
#define CC 5
#define TAG_START 3
#define TAG_STOP 4
#define IMPOSSIBLE_F (-1e4f)

// warp id from (mt, rt, kh): wid = mt + 4*rt + 8*kh
#define mt_from(mt_, rt_, kh_) ((mt_) + 4 * (rt_) + 8 * (kh_))

typedef unsigned long long ull;

__device__ __forceinline__ float tf32r(float x) {
    uint32_t u; asm("cvt.rna.tf32.f32 %0, %1;" : "=r"(u) : "f"(x));
    return __uint_as_float(u);
}
__device__ __forceinline__ float tanh_a(float x) {
    float r; asm("tanh.approx.f32 %0, %1;" : "=f"(r) : "f"(x)); return r;
}

// ---------------- scratch (device globals; no cudaMalloc allowed) -------------
__device__ float g_embx [(size_t)LL * BB * EE];
__device__ float g_bufA [(size_t)LL * BB * HID];
__device__ float g_bufB [(size_t)LL * BB * HID];
__device__ float g_gates[(size_t)2 * NG * MM];        // G^T: [dir][n][m]
__device__ float g_emit [(size_t)LL * BB * CC];
__device__ int   g_bp   [(size_t)LL * BB * CC];
__device__ unsigned g_flags[128 * 32];                // per-CTA flag, own 128B line

__global__ void init_bar_k() {
    int i = blockIdx.x * blockDim.x + threadIdx.x;
    if (i < 128 * 32) g_flags[i] = 0u;
}

// ---------------- embedding gather --------------------------------------------
__global__ void embed_k(const int* __restrict__ xs, const float* __restrict__ emb,
                        float* __restrict__ X)
{
    size_t i = (size_t)blockIdx.x * blockDim.x + threadIdx.x;
    size_t total = (size_t)LL * BB * (EE / 4);
    if (i >= total) return;
    int e4 = (int)(i % (EE / 4));
    size_t p = i / (EE / 4);
    int b = (int)(p % BB);
    int t = (int)(p / BB);
    int tok = xs[(size_t)b * LL + t];
    *(float4*)&X[p * EE + e4 * 4] = *(const float4*)&emb[(size_t)tok * EE + e4 * 4];
}

// ---------------- wmma tf32 input-projection GEMM, transposed output ----------
// GT[dir][n][m] = A[m,:]·W[dir][n,:] + bias[n]
#define GP 36
#define GBUF (128 * GP)
#define BT_STRIDE 132
#define GSM_TOT ((4 * GBUF + 16 * BT_STRIDE) * 4)     // 82176 bytes

__global__ __launch_bounds__(256) void gemm_wmma_k(
    const float* __restrict__ A,
    const float* __restrict__ W0, const float* __restrict__ W1,
    const float* __restrict__ bias0, const float* __restrict__ bias1,
    float* __restrict__ G, int K)
{
    extern __shared__ float sm[];
    float* Abuf[2] = { sm,             sm + GBUF     };
    float* Wbuf[2] = { sm + 2 * GBUF,  sm + 3 * GBUF };
    float* btile   = sm + 4 * GBUF;                   // [16][132], rows identical

    int tid = threadIdx.x, wid = tid >> 5;
    int m0 = blockIdx.x * 128;
    int n0 = blockIdx.y * 128;
    int dir = blockIdx.z;
    const float* W    = dir ? W1 : W0;
    const float* bias = dir ? bias1 : bias0;
    float* Gt = G + (size_t)dir * NG * MM;

    int wm = wid >> 2;
    int wn = wid & 3;

#pragma unroll
    for (int u = 0; u < 8; u++) {
        int idx = tid + u * 256;
        int r = idx >> 7, c = idx & 127;
        btile[r * BT_STRIDE + c] = bias[n0 + c];
    }

    auto stage = [&](int c, int buf) {
        const float* Asrc = A + (size_t)m0 * K + c * 32;
        const float* Wsrc = W + (size_t)n0 * K + c * 32;
        float* ad = Abuf[buf];
        float* wd = Wbuf[buf];
#pragma unroll
        for (int u = 0; u < 4; u++) {
            int idx = tid + u * 256;
            int row = idx >> 3, c4 = idx & 7;
            float4 v = *(const float4*)&Asrc[(size_t)row * K + c4 * 4];
            v.x = tf32r(v.x); v.y = tf32r(v.y); v.z = tf32r(v.z); v.w = tf32r(v.w);
            *(float4*)&ad[row * GP + c4 * 4] = v;
            float4 q = *(const float4*)&Wsrc[(size_t)row * K + c4 * 4];
            q.x = tf32r(q.x); q.y = tf32r(q.y); q.z = tf32r(q.z); q.w = tf32r(q.w);
            *(float4*)&wd[row * GP + c4 * 4] = q;
        }
    };

    stage(0, 0);
    __syncthreads();

    wmma::fragment<wmma::accumulator, 16, 16, 8, float> acc[4][2];
#pragma unroll
    for (int i = 0; i < 4; i++)
#pragma unroll
        for (int j = 0; j < 2; j++)
            wmma::load_matrix_sync(acc[i][j], btile + wn * 32 + j * 16,
                                   BT_STRIDE, wmma::mem_row_major);

    const int NC = K >> 5;
    for (int c = 0; c < NC; c++) {
        int cur = c & 1;
        if (c + 1 < NC) stage(c + 1, cur ^ 1);

        const float* ab = Abuf[cur] + wm * 64 * GP;
        const float* wb = Wbuf[cur] + wn * 32 * GP;
#pragma unroll
        for (int kk = 0; kk < 4; kk++) {
            wmma::fragment<wmma::matrix_a, 16, 16, 8, wmma::precision::tf32,
                           wmma::row_major> af[4];
            wmma::fragment<wmma::matrix_b, 16, 16, 8, wmma::precision::tf32,
                           wmma::col_major> bf[2];
#pragma unroll
            for (int i = 0; i < 4; i++)
                wmma::load_matrix_sync(af[i], ab + i * 16 * GP + kk * 8, GP);
#pragma unroll
            for (int j = 0; j < 2; j++)
                wmma::load_matrix_sync(bf[j], wb + j * 16 * GP + kk * 8, GP);
#pragma unroll
            for (int i = 0; i < 4; i++)
#pragma unroll
                for (int j = 0; j < 2; j++)
                    wmma::mma_sync(acc[i][j], af[i], bf[j], acc[i][j]);
        }
        __syncthreads();
    }

#pragma unroll
    for (int i = 0; i < 4; i++)
#pragma unroll
        for (int j = 0; j < 2; j++) {
            float* gt = Gt + (size_t)(n0 + wn * 32 + j * 16) * MM
                           + (m0 + wm * 64 + i * 16);
            wmma::store_matrix_sync(gt, acc[i][j], MM, wmma::mem_col_major);
        }
}

// ---------------- persistent per-layer LSTM recurrence (tensor-core dot) ------
// 64 CTAs: dir = bx>>5, unit group j0 = (bx&31)*8.  512 threads.
// Dot: out[64b][32r] = hs[64][256] @ ws2[256][32]  via wmma tf32.
//   warp w (0..15): mt = w&3 (16-batch), rt = (w>>2)&1 (16-row), kh = w>>3.
//   Each warp: 16 mma of 16x16x8 over its K-half (128).
// part[w][16m][16r] (ld 20) summed in activation (thread = (b, unit), 512 = 64x8).
#define HS_S  264                        // hs row stride (floats)
#define WS_LD 36                         // ws2 [256][WS_LD] row-major (k, r=0..31)
#define P_LD  20
#define SM_WS 0                          // 256*36 = 9216 floats
#define SM_HS 9216                       // 64*264 = 16896
#define SM_GS (SM_HS + 64 * HS_S)        // 32*64  = 2048
#define SM_PT (SM_GS + 2048)             // 16*16*P_LD = 5120
#define SM_HO (SM_PT + 16 * 16 * P_LD)   // 8*64 = 512
#define LSTM_SMEM ((SM_HO + 512) * 4)    // 135168 bytes

__global__ __launch_bounds__(512, 1) void lstm_layer_k(
    const float* __restrict__ Gt,
    const float* __restrict__ Whh0, const float* __restrict__ Whh1,
    float* __restrict__ y, int lbase)
{
    extern __shared__ float sm[];
    float* ws2  = sm + SM_WS;
    float* hs   = sm + SM_HS;
    float* Gs   = sm + SM_GS;
    float* part = sm + SM_PT;
    float* hout = sm + SM_HO;

    int bx  = blockIdx.x;
    int dir = bx >> 5;
    int cg  = bx & 31;
    int j0  = cg * 8;
    int tid = threadIdx.x;
    int wid = tid >> 5;
    int mt = wid & 3, rt = (wid >> 2) & 1, kh = wid >> 3;
    const float* Whh = dir ? Whh1 : Whh0;
    const float* Gd  = Gt + (size_t)dir * NG * MM;

    // ---- stage Whh transposed into smem once: ws2[k][r], r = g*8+u ----------
#pragma unroll
    for (int u = 0; u < 16; u++) {
        int idx = tid + u * 512;         // 8192 scalars
        int k = idx >> 5, r = idx & 31;
        int g = r >> 3, un = r & 7;
        ws2[k * WS_LD + r] = tf32r(Whh[(size_t)(g * 256 + j0 + un) * HH + k]);
    }

    int ab = tid & 63, au = tid >> 6;    // activation identity: (batch, unit 0..7)
    int am = ab & 15, amt = ab >> 4;
    float cst = 0.f;

    // G gather indices: 2048 values (32 rows x 64 b), 4 per thread
    size_t gaddr[4];
    int grow[4], gbv[4];
#pragma unroll
    for (int u = 0; u < 4; u++) {
        int v = tid + u * 512;
        int r = v >> 6, bb = v & 63;
        grow[u] = r; gbv[u] = bb;
        gaddr[u] = (size_t)((r >> 3) * 256 + j0 + (r & 7)) * MM + bb;
    }

    unsigned* myflag = &g_flags[(dir * 32 + cg) * 32];
    __syncthreads();                     // ws2 ready

    // preload input-projection gates for s = 0
    float glo[4];
    {
        int t0 = dir ? (LL - 1) : 0;
#pragma unroll
        for (int u = 0; u < 4; u++)
            glo[u] = Gd[gaddr[u] + (size_t)t0 * 64];
    }

    for (int s = 0; s < LL; s++) {
        int t     = dir ? (LL - 1 - s) : s;
        int tprev = dir ? (t + 1) : (t - 1);

        if (s > 0) {
            // stage h_prev: 64 b x 256 k = 4096 float4, 8 per thread
            const float* yb = y + ((size_t)tprev * BB) * HID + dir * HH;
#pragma unroll
            for (int u = 0; u < 8; u++) {
                int v = tid + u * 512;
                int b2 = v >> 6, k4 = v & 63;
                float4 hv = *(const float4*)&yb[(size_t)b2 * HID + k4 * 4];
                *(float4*)&hs[b2 * HS_S + k4 * 4] = hv;
            }
        }
#pragma unroll
        for (int u = 0; u < 4; u++)
            Gs[grow[u] * 64 + gbv[u]] = glo[u];
        __syncthreads();                 // hs + Gs ready

        if (s > 0) {
            // wmma dot: warp (mt, rt, kh)
            wmma::fragment<wmma::accumulator, 16, 16, 8, float> acc;
            wmma::fill_fragment(acc, 0.f);
            const float* hb = hs + mt * 16 * HS_S + kh * 128;
            const float* wb = ws2 + kh * 128 * WS_LD + rt * 16;
#pragma unroll
            for (int kf = 0; kf < 16; kf++) {
                wmma::fragment<wmma::matrix_a, 16, 16, 8, wmma::precision::tf32,
                               wmma::row_major> af;
                wmma::fragment<wmma::matrix_b, 16, 16, 8, wmma::precision::tf32,
                               wmma::row_major> bf;
                wmma::load_matrix_sync(af, hb + kf * 8, HS_S);
#pragma unroll
                for (int e = 0; e < af.num_elements; e++)
                    af.x[e] = wmma::__float_to_tf32(af.x[e]);
                wmma::load_matrix_sync(bf, wb + kf * 8 * WS_LD, WS_LD);
                wmma::mma_sync(acc, af, bf, acc);
            }
            wmma::store_matrix_sync(part + wid * (16 * P_LD), acc, P_LD,
                                    wmma::mem_row_major);
        }
        __syncthreads();                 // part ready

        // activation: thread (ab, au) owns one (batch, unit)
        {
            float pre[4];
#pragma unroll
            for (int g = 0; g < 4; g++) {
                int r = g * 8 + au;
                float a = Gs[r * 64 + ab];
                if (s > 0) {
                    int rt2 = r >> 4, rr = r & 15;
                    a += part[(mt_from(amt, rt2, 0)) * (16 * P_LD) + am * P_LD + rr];
                    a += part[(mt_from(amt, rt2, 1)) * (16 * P_LD) + am * P_LD + rr];
                }
                pre[g] = a;
            }
            float ig = 0.5f * (1.f + tanh_a(0.5f * pre[0]));
            float fg = 0.5f * (1.f + tanh_a(0.5f * pre[1]));
            float gg = tanh_a(pre[2]);
            float og = 0.5f * (1.f + tanh_a(0.5f * pre[3]));
            cst = fg * cst + ig * gg;
            hout[au * 64 + ab] = og * tanh_a(cst);
        }
        __syncthreads();                 // hout ready

        if (tid < 64) {
            float* yt = &y[((size_t)t * BB + tid) * HID + dir * HH + j0];
            float4 h0, h1;
            h0.x = hout[0 * 64 + tid]; h0.y = hout[1 * 64 + tid];
            h0.z = hout[2 * 64 + tid]; h0.w = hout[3 * 64 + tid];
            h1.x = hout[4 * 64 + tid]; h1.y = hout[5 * 64 + tid];
            h1.z = hout[6 * 64 + tid]; h1.w = hout[7 * 64 + tid];
            *(float4*)&yt[0] = h0;
            *(float4*)&yt[4] = h1;
        }
        __syncthreads();                 // y writes done

        if (s + 1 < LL) {
            // prefetch next step's gates BEFORE the spin
            int tn = dir ? (LL - 2 - s) : (s + 1);
#pragma unroll
            for (int u = 0; u < 4; u++)
                glo[u] = Gd[gaddr[u] + (size_t)tn * 64];

            unsigned tgt = (unsigned)(lbase + s + 1);
            if (tid == 0)
                asm volatile("st.release.gpu.global.u32 [%0], %1;"
                             :: "l"(myflag), "r"(tgt) : "memory");
            if (tid < 32) {
                unsigned* fl = &g_flags[(dir * 32 + tid) * 32];
                unsigned v;
                do {
                    asm volatile("ld.acquire.gpu.global.u32 %0, [%1];"
                                 : "=r"(v) : "l"(fl));
                } while (v < tgt);
            }
            __syncthreads();
        }
    }
}

// ---------------- FC -----------------------------------------------------------
__global__ void fc_k(const float* __restrict__ feat, const float* __restrict__ Wfc,
                     const float* __restrict__ bfc, float* __restrict__ emit)
{
    int gw = (int)(((size_t)blockIdx.x * blockDim.x + threadIdx.x) >> 5);
    int lane = threadIdx.x & 31;
    if (gw >= LL * BB) return;
    const float* f = feat + (size_t)gw * HID;
    float acc[CC] = {0.f, 0.f, 0.f, 0.f, 0.f};
#pragma unroll
    for (int i = 0; i < HID / 32; i++) {
        int k = lane + i * 32;
        float fv = f[k];
#pragma unroll
        for (int cc = 0; cc < CC; cc++) acc[cc] += fv * Wfc[cc * HID + k];
    }
#pragma unroll
    for (int off = 16; off > 0; off >>= 1)
#pragma unroll
        for (int cc = 0; cc < CC; cc++)
            acc[cc] += __shfl_down_sync(0xffffffffu, acc[cc], off);
    if (lane == 0)
#pragma unroll
        for (int cc = 0; cc < CC; cc++)
            emit[(size_t)gw * CC + cc] = acc[cc] + bfc[cc];
}

// ---------------- Viterbi + backtrace ------------------------------------------
__global__ void viterbi_k(const float* __restrict__ emit, const float* __restrict__ trans,
                          int* __restrict__ bp, float* __restrict__ out, long long osz)
{
    int b = blockIdx.x;
    int lane = threadIdx.x;
    float tr[CC];
    if (lane < CC)
#pragma unroll
        for (int f = 0; f < CC; f++) tr[f] = trans[lane * CC + f];
    float score = (lane == TAG_START) ? 0.f : IMPOSSIBLE_F;

    for (int t = 0; t < LL; t++) {
        float sc[CC];
#pragma unroll
        for (int f = 0; f < CC; f++) sc[f] = __shfl_sync(0xffffffffu, score, f);
        if (lane < CC) {
            float best = sc[0] + tr[0];
            int arg = 0;
#pragma unroll
            for (int f = 1; f < CC; f++) {
                float v = sc[f] + tr[f];
                if (v > best) { best = v; arg = f; }
            }
            bp[((size_t)t * BB + b) * CC + lane] = arg;
            score = best + emit[((size_t)t * BB + b) * CC + lane];
        }
    }
    if (lane < CC) score += trans[TAG_STOP * CC + lane];
    float sc[CC];
#pragma unroll
    for (int f = 0; f < CC; f++) sc[f] = __shfl_sync(0xffffffffu, score, f);
    if (lane == 0) {
        float best = sc[0];
        int tag = 0;
#pragma unroll
        for (int f = 1; f < CC; f++)
            if (sc[f] > best) { best = sc[f]; tag = f; }
        if (b < osz) out[b] = best;
        long long tb = 64;
        long long o = tb + (long long)b * LL + (LL - 1);
        if (o < osz) out[o] = (float)tag;
        for (int t = LL - 1; t >= 1; t--) {
            tag = bp[((size_t)t * BB + b) * CC + tag];
            o = tb + (long long)b * LL + (t - 1);
            if (o < osz) out[o] = (float)tag;
        }
    }
}

// ---------------- features [t][b][k] -> out [b][t][k] --------------------------
__global__ void feat_out_k(const float* __restrict__ feat, float* __restrict__ out,
                           long long osz)
{
    size_t i = (size_t)blockIdx.x * blockDim.x + threadIdx.x;
    size_t total = (size_t)LL * BB * HID / 4;
    if (i >= total) return;
    int k4 = (int)(i % (HID / 4));
    size_t p = i / (HID / 4);
    int b = (int)(p % BB);
    int t = (int)(p / BB);
    long long o = 32832LL + ((long long)b * LL + t) * HID + k4 * 4;
    if (o + 3 < osz)
        *(float4*)&out[o] = *(const float4*)&feat[p * HID + k4 * 4];
}

__global__ void mask_out_k(float* __restrict__ out, long long osz)
{
    long long i = (long long)blockIdx.x * blockDim.x + threadIdx.x;
    if (i >= (long long)BB * LL) return;
    long long o = 16810048LL + i;
    if (o < osz) out[o] = 1.0f;
}

// ---------------- launch --------------------------------------------------------
extern "C" void kernel_launch(void* const* d_in, const int* in_sizes, int n_in,
                              void* d_out, int out_size)
{
    const int*   xs    = (const int*)  d_in[0];
    const float* emb   = (const float*)d_in[1];
    const float* Wih0  = (const float*)d_in[2];
    const float* Whh0  = (const float*)d_in[3];
    const float* b0    = (const float*)d_in[4];
    const float* WihL  = (const float*)d_in[5];
    const float* WhhL  = (const float*)d_in[6];
    const float* bL    = (const float*)d_in[7];
    const float* Wfc   = (const float*)d_in[8];
    const float* bfc   = (const float*)d_in[9];
    const float* trans = (const float*)d_in[10];
    float* out = (float*)d_out;
    long long osz = out_size;

    float *pX, *pA, *pB, *pG, *pE;
    int* pBP;
    cudaGetSymbolAddress((void**)&pX,  g_embx);
    cudaGetSymbolAddress((void**)&pA,  g_bufA);
    cudaGetSymbolAddress((void**)&pB,  g_bufB);
    cudaGetSymbolAddress((void**)&pG,  g_gates);
    cudaGetSymbolAddress((void**)&pE,  g_emit);
    cudaGetSymbolAddress((void**)&pBP, g_bp);

    cudaFuncSetAttribute(lstm_layer_k, cudaFuncAttributeMaxDynamicSharedMemorySize,
                         LSTM_SMEM);
    cudaFuncSetAttribute(gemm_wmma_k, cudaFuncAttributeMaxDynamicSharedMemorySize,
                         GSM_TOT);

    init_bar_k<<<16, 256>>>();

    {
        size_t total = (size_t)LL * BB * (EE / 4);
        embed_k<<<(unsigned)((total + 255) / 256), 256>>>(xs, emb, pX);
    }

    const float* x = pX;
    int K = EE;
    for (int l = 0; l < 4; l++) {
        const float *WihF, *WihB, *WhhF, *WhhB, *bF, *bBk;
        if (l == 0) {
            WihF = Wih0;                 WihB = Wih0 + (size_t)NG * EE;
            WhhF = Whh0;                 WhhB = Whh0 + (size_t)NG * HH;
            bF   = b0;                   bBk  = b0 + NG;
        } else {
            size_t base = (size_t)(l - 1) * 2;
            WihF = WihL + base * NG * HID;       WihB = WihL + (base + 1) * NG * HID;
            WhhF = WhhL + base * NG * HH;        WhhB = WhhL + (base + 1) * NG * HH;
            bF   = bL + base * NG;               bBk  = bL + (base + 1) * NG;
        }
        float* y = (l & 1) ? pB : pA;

        dim3 ggrid(MM / 128, NG / 128, 2);
        gemm_wmma_k<<<ggrid, 256, GSM_TOT>>>(x, WihF, WihB, bF, bBk, pG, K);

        lstm_layer_k<<<64, 512, LSTM_SMEM>>>(pG, WhhF, WhhB, y, l * LL);

        x = y;
        K = HID;
    }

    fc_k<<<(LL * BB * 32) / 256, 256>>>(x, Wfc, bfc, pE);
    viterbi_k<<<BB, 32>>>(pE, trans, pBP, out, osz);
    {
        size_t total = (size_t)LL * BB * HID / 4;
        feat_out_k<<<(unsigned)((total + 255) / 256), 256>>>(x, out, osz);
    }
    mask_out_k<<<(BB * LL + 255) / 256, 256>>>(out, osz);
}

// round 14
// speedup vs baseline: 1.5006x; 1.5006x over previous
#include <cuda_runtime.h>
#include <math.h>
#include <stdint.h>
#include <mma.h>
#include <cuda_fp16.h>

using namespace nvcuda;

#define LL 512
#define BB 64
#define EE 256
#define HH 256
#define HID 512
#define NG 1024      // 4*H gate rows
#define MM 32768     // LL*BB
#define CC 5
#define TAG_START 3
#define TAG_STOP 4
#define IMPOSSIBLE_F (-1e4f)

typedef unsigned long long ull;

__device__ __forceinline__ float tf32r(float x) {
    uint32_t u; asm("cvt.rna.tf32.f32 %0, %1;" : "=r"(u) : "f"(x));
    return __uint_as_float(u);
}
__device__ __forceinline__ float tanh_a(float x) {
    float r; asm("tanh.approx.f32 %0, %1;" : "=f"(r) : "f"(x)); return r;
}
__device__ __forceinline__ uint32_t smem_u32(const void* p) {
    uint32_t a;
    asm("{ .reg .u64 t; cvta.to.shared.u64 t, %1; cvt.u32.u64 %0, t; }" : "=r"(a) : "l"(p));
    return a;
}
#define CLUSTER_SYNC() do { \
    asm volatile("barrier.cluster.arrive.aligned;" ::: "memory"); \
    asm volatile("barrier.cluster.wait.aligned;" ::: "memory"); \
} while (0)

// ---------------- scratch (device globals; no cudaMalloc allowed) -------------
__device__ float g_embx [(size_t)LL * BB * EE];
__device__ float g_bufA [(size_t)LL * BB * HID];
__device__ float g_bufB [(size_t)LL * BB * HID];
__device__ float g_gates[(size_t)2 * NG * MM];        // G^T: [dir][n][m]
__device__ float g_emit [(size_t)LL * BB * CC];
__device__ int   g_bp   [(size_t)LL * BB * CC];

// ---------------- embedding gather --------------------------------------------
__global__ void embed_k(const int* __restrict__ xs, const float* __restrict__ emb,
                        float* __restrict__ X)
{
    size_t i = (size_t)blockIdx.x * blockDim.x + threadIdx.x;
    size_t total = (size_t)LL * BB * (EE / 4);
    if (i >= total) return;
    int e4 = (int)(i % (EE / 4));
    size_t p = i / (EE / 4);
    int b = (int)(p % BB);
    int t = (int)(p / BB);
    int tok = xs[(size_t)b * LL + t];
    *(float4*)&X[p * EE + e4 * 4] = *(const float4*)&emb[(size_t)tok * EE + e4 * 4];
}

// ---------------- wmma tf32 input-projection GEMM, transposed output ----------
// GT[dir][n][m] = A[m,:]·W[dir][n,:] + bias[n]
#define GP 36
#define GBUF (128 * GP)
#define BT_STRIDE 132
#define GSM_TOT ((4 * GBUF + 16 * BT_STRIDE) * 4)     // 82176 bytes

__global__ __launch_bounds__(256) void gemm_wmma_k(
    const float* __restrict__ A,
    const float* __restrict__ W0, const float* __restrict__ W1,
    const float* __restrict__ bias0, const float* __restrict__ bias1,
    float* __restrict__ G, int K)
{
    extern __shared__ float sm[];
    float* Abuf[2] = { sm,             sm + GBUF     };
    float* Wbuf[2] = { sm + 2 * GBUF,  sm + 3 * GBUF };
    float* btile   = sm + 4 * GBUF;

    int tid = threadIdx.x, wid = tid >> 5;
    int m0 = blockIdx.x * 128;
    int n0 = blockIdx.y * 128;
    int dir = blockIdx.z;
    const float* W    = dir ? W1 : W0;
    const float* bias = dir ? bias1 : bias0;
    float* Gt = G + (size_t)dir * NG * MM;

    int wm = wid >> 2;
    int wn = wid & 3;

#pragma unroll
    for (int u = 0; u < 8; u++) {
        int idx = tid + u * 256;
        int r = idx >> 7, c = idx & 127;
        btile[r * BT_STRIDE + c] = bias[n0 + c];
    }

    auto stage = [&](int c, int buf) {
        const float* Asrc = A + (size_t)m0 * K + c * 32;
        const float* Wsrc = W + (size_t)n0 * K + c * 32;
        float* ad = Abuf[buf];
        float* wd = Wbuf[buf];
#pragma unroll
        for (int u = 0; u < 4; u++) {
            int idx = tid + u * 256;
            int row = idx >> 3, c4 = idx & 7;
            float4 v = *(const float4*)&Asrc[(size_t)row * K + c4 * 4];
            v.x = tf32r(v.x); v.y = tf32r(v.y); v.z = tf32r(v.z); v.w = tf32r(v.w);
            *(float4*)&ad[row * GP + c4 * 4] = v;
            float4 q = *(const float4*)&Wsrc[(size_t)row * K + c4 * 4];
            q.x = tf32r(q.x); q.y = tf32r(q.y); q.z = tf32r(q.z); q.w = tf32r(q.w);
            *(float4*)&wd[row * GP + c4 * 4] = q;
        }
    };

    stage(0, 0);
    __syncthreads();

    wmma::fragment<wmma::accumulator, 16, 16, 8, float> acc[4][2];
#pragma unroll
    for (int i = 0; i < 4; i++)
#pragma unroll
        for (int j = 0; j < 2; j++)
            wmma::load_matrix_sync(acc[i][j], btile + wn * 32 + j * 16,
                                   BT_STRIDE, wmma::mem_row_major);

    const int NC = K >> 5;
    for (int c = 0; c < NC; c++) {
        int cur = c & 1;
        if (c + 1 < NC) stage(c + 1, cur ^ 1);

        const float* ab = Abuf[cur] + wm * 64 * GP;
        const float* wb = Wbuf[cur] + wn * 32 * GP;
#pragma unroll
        for (int kk = 0; kk < 4; kk++) {
            wmma::fragment<wmma::matrix_a, 16, 16, 8, wmma::precision::tf32,
                           wmma::row_major> af[4];
            wmma::fragment<wmma::matrix_b, 16, 16, 8, wmma::precision::tf32,
                           wmma::col_major> bf[2];
#pragma unroll
            for (int i = 0; i < 4; i++)
                wmma::load_matrix_sync(af[i], ab + i * 16 * GP + kk * 8, GP);
#pragma unroll
            for (int j = 0; j < 2; j++)
                wmma::load_matrix_sync(bf[j], wb + j * 16 * GP + kk * 8, GP);
#pragma unroll
            for (int i = 0; i < 4; i++)
#pragma unroll
                for (int j = 0; j < 2; j++)
                    wmma::mma_sync(acc[i][j], af[i], bf[j], acc[i][j]);
        }
        __syncthreads();
    }

#pragma unroll
    for (int i = 0; i < 4; i++)
#pragma unroll
        for (int j = 0; j < 2; j++) {
            float* gt = Gt + (size_t)(n0 + wn * 32 + j * 16) * MM
                           + (m0 + wm * 64 + i * 16);
            wmma::store_matrix_sync(gt, acc[i][j], MM, wmma::mem_col_major);
        }
}

// ---------------- cluster-local persistent LSTM recurrence ---------------------
// 32 CTAs in 8 clusters of 4. bx: cu = bx&3 (n-slice: units cu*64..+63),
// cid = bx>>2: dir = cid>>2, bg = cid&3 (batches bg*16..+15). 256 threads.
// Per step: C[16b][256n] = h[16b][256k](fp16) @ WB[256k][256n](fp16, smem),
// activation (c in regs), h fp16 -> own + 3 peers' hA (double-buffered),
// ONE cluster sync per step. No grid sync at all.
#define WB_LD 272                        // fp16 elements per k-row
#define HA_LD 264                        // fp16 elements per b-row
#define CS_LD 260                        // fp32 elements per b-row
#define OFF_WB 0
#define OFF_HA0 139264                   // 256*272*2
#define OFF_HA1 (OFF_HA0 + 16 * HA_LD * 2)
#define OFF_CS  (OFF_HA1 + 16 * HA_LD * 2)
#define LSTM_SMEM (OFF_CS + 16 * CS_LD * 4)   // 172800 bytes

__global__ __launch_bounds__(256, 1) __cluster_dims__(4, 1, 1)
void lstm_layer_k(const float* __restrict__ Gt,
                  const float* __restrict__ Whh0, const float* __restrict__ Whh1,
                  float* __restrict__ y)
{
    extern __shared__ char smc[];
    half*  WB  = (half*)(smc + OFF_WB);
    half*  hA[2] = { (half*)(smc + OFF_HA0), (half*)(smc + OFF_HA1) };
    float* Cs  = (float*)(smc + OFF_CS);

    int bx  = blockIdx.x;
    int cu  = bx & 3;
    int cid = bx >> 2;
    int dir = cid >> 2;
    int bg  = cid & 3;
    int tid = threadIdx.x, wid = tid >> 5;
    const float* Whh = dir ? Whh1 : Whh0;
    const float* Gd  = Gt + (size_t)dir * NG * MM;

    // ---- load weight slice fp32->fp16: WB[k][n_l], n_l = g*64+u -------------
#pragma unroll 4
    for (int it = 0; it < 64; it++) {
        int flat = tid + it * 256;       // 16384 float4
        int n_l = flat >> 6, k4 = flat & 63;
        int g = n_l >> 6, u = n_l & 63;
        float4 v = *(const float4*)&Whh[(size_t)(g * 256 + cu * 64 + u) * HH + k4 * 4];
        WB[(k4 * 4 + 0) * WB_LD + n_l] = __float2half_rn(v.x);
        WB[(k4 * 4 + 1) * WB_LD + n_l] = __float2half_rn(v.y);
        WB[(k4 * 4 + 2) * WB_LD + n_l] = __float2half_rn(v.z);
        WB[(k4 * 4 + 3) * WB_LD + n_l] = __float2half_rn(v.w);
    }

    int b  = tid & 15;                   // batch (local)
    int ug = tid >> 4;                   // unit group (0..15), u = ug*4..+3
    float cst[4] = {0.f, 0.f, 0.f, 0.f};

    uint32_t habase[2] = { smem_u32(hA[0]), smem_u32(hA[1]) };

    __syncthreads();
    CLUSTER_SYNC();                      // weights staged cluster-wide

    // G prefetch for s = 0
    float gpre[16];
    {
        int t0 = dir ? (LL - 1) : 0;
#pragma unroll
        for (int g = 0; g < 4; g++)
#pragma unroll
            for (int i = 0; i < 4; i++)
                gpre[g * 4 + i] =
                    Gd[(size_t)(g * 256 + cu * 64 + ug * 4 + i) * MM
                       + (size_t)t0 * 64 + bg * 16 + b];
    }

    for (int s = 0; s < LL; s++) {
        int t = dir ? (LL - 1 - s) : s;

        if (s > 0) {
            // wmma: warp w owns n in [w*32, w*32+32)
            const half* ha = hA[s & 1];
            const half* wb0 = WB + wid * 32;
            wmma::fragment<wmma::accumulator, 16, 16, 16, float> acc0, acc1;
            wmma::fill_fragment(acc0, 0.f);
            wmma::fill_fragment(acc1, 0.f);
#pragma unroll
            for (int kf = 0; kf < 16; kf++) {
                wmma::fragment<wmma::matrix_a, 16, 16, 16, half,
                               wmma::row_major> af;
                wmma::fragment<wmma::matrix_b, 16, 16, 16, half,
                               wmma::row_major> bf0, bf1;
                wmma::load_matrix_sync(af, ha + kf * 16, HA_LD);
                wmma::load_matrix_sync(bf0, wb0 + (kf * 16) * WB_LD, WB_LD);
                wmma::load_matrix_sync(bf1, wb0 + (kf * 16) * WB_LD + 16, WB_LD);
                wmma::mma_sync(acc0, af, bf0, acc0);
                wmma::mma_sync(acc1, af, bf1, acc1);
            }
            wmma::store_matrix_sync(Cs + wid * 32,      acc0, CS_LD,
                                    wmma::mem_row_major);
            wmma::store_matrix_sync(Cs + wid * 32 + 16, acc1, CS_LD,
                                    wmma::mem_row_major);
        }
        __syncthreads();                 // Cs ready

        // activation: thread (b, ug) owns units u = ug*4..+3
        half* hn = hA[(s + 1) & 1];
        uint32_t hdst = habase[(s + 1) & 1]
                      + (uint32_t)(b * HA_LD + cu * 64 + ug * 4) * 2;
        float hv[4];
#pragma unroll
        for (int i = 0; i < 4; i++) {
            float pi = gpre[0 * 4 + i];
            float pf = gpre[1 * 4 + i];
            float pg = gpre[2 * 4 + i];
            float po = gpre[3 * 4 + i];
            if (s > 0) {
                const float* cb = Cs + b * CS_LD + ug * 4 + i;
                pi += cb[0 * 64];
                pf += cb[1 * 64];
                pg += cb[2 * 64];
                po += cb[3 * 64];
            }
            float ig = 0.5f * (1.f + tanh_a(0.5f * pi));
            float fg = 0.5f * (1.f + tanh_a(0.5f * pf));
            float gg = tanh_a(pg);
            float og = 0.5f * (1.f + tanh_a(0.5f * po));
            cst[i] = fg * cst[i] + ig * gg;
            hv[i] = og * tanh_a(cst[i]);
        }
        // pack to fp16 and broadcast to all 4 cluster CTAs' hA
        {
            half2 p0 = __halves2half2(__float2half_rn(hv[0]), __float2half_rn(hv[1]));
            half2 p1 = __halves2half2(__float2half_rn(hv[2]), __float2half_rn(hv[3]));
            uint32_t u0 = *(uint32_t*)&p0;
            uint32_t u1 = *(uint32_t*)&p1;
#pragma unroll
            for (int r = 0; r < 4; r++) {
                uint32_t ra;
                asm volatile("mapa.shared::cluster.u32 %0, %1, %2;"
                             : "=r"(ra) : "r"(hdst), "r"(r));
                asm volatile("st.shared::cluster.u32 [%0], %1;"
                             :: "r"(ra), "r"(u0) : "memory");
                asm volatile("st.shared::cluster.u32 [%0], %1;"
                             :: "r"(ra + 4), "r"(u1) : "memory");
            }
        }
        // y writeout (fp32, for next layer / features)
        {
            float4 v = make_float4(hv[0], hv[1], hv[2], hv[3]);
            *(float4*)&y[((size_t)t * BB + bg * 16 + b) * HID
                         + dir * HH + cu * 64 + ug * 4] = v;
        }
        // prefetch G for next step
        if (s + 1 < LL) {
            int tn = dir ? (LL - 2 - s) : (s + 1);
#pragma unroll
            for (int g = 0; g < 4; g++)
#pragma unroll
                for (int i = 0; i < 4; i++)
                    gpre[g * 4 + i] =
                        Gd[(size_t)(g * 256 + cu * 64 + ug * 4 + i) * MM
                           + (size_t)tn * 64 + bg * 16 + b];
        }
        CLUSTER_SYNC();                  // h published cluster-wide
    }
}

// ---------------- FC -----------------------------------------------------------
__global__ void fc_k(const float* __restrict__ feat, const float* __restrict__ Wfc,
                     const float* __restrict__ bfc, float* __restrict__ emit)
{
    int gw = (int)(((size_t)blockIdx.x * blockDim.x + threadIdx.x) >> 5);
    int lane = threadIdx.x & 31;
    if (gw >= LL * BB) return;
    const float* f = feat + (size_t)gw * HID;
    float acc[CC] = {0.f, 0.f, 0.f, 0.f, 0.f};
#pragma unroll
    for (int i = 0; i < HID / 32; i++) {
        int k = lane + i * 32;
        float fv = f[k];
#pragma unroll
        for (int cc = 0; cc < CC; cc++) acc[cc] += fv * Wfc[cc * HID + k];
    }
#pragma unroll
    for (int off = 16; off > 0; off >>= 1)
#pragma unroll
        for (int cc = 0; cc < CC; cc++)
            acc[cc] += __shfl_down_sync(0xffffffffu, acc[cc], off);
    if (lane == 0)
#pragma unroll
        for (int cc = 0; cc < CC; cc++)
            emit[(size_t)gw * CC + cc] = acc[cc] + bfc[cc];
}

// ---------------- Viterbi + backtrace ------------------------------------------
__global__ void viterbi_k(const float* __restrict__ emit, const float* __restrict__ trans,
                          int* __restrict__ bp, float* __restrict__ out, long long osz)
{
    int b = blockIdx.x;
    int lane = threadIdx.x;
    float tr[CC];
    if (lane < CC)
#pragma unroll
        for (int f = 0; f < CC; f++) tr[f] = trans[lane * CC + f];
    float score = (lane == TAG_START) ? 0.f : IMPOSSIBLE_F;

    for (int t = 0; t < LL; t++) {
        float sc[CC];
#pragma unroll
        for (int f = 0; f < CC; f++) sc[f] = __shfl_sync(0xffffffffu, score, f);
        if (lane < CC) {
            float best = sc[0] + tr[0];
            int arg = 0;
#pragma unroll
            for (int f = 1; f < CC; f++) {
                float v = sc[f] + tr[f];
                if (v > best) { best = v; arg = f; }
            }
            bp[((size_t)t * BB + b) * CC + lane] = arg;
            score = best + emit[((size_t)t * BB + b) * CC + lane];
        }
    }
    if (lane < CC) score += trans[TAG_STOP * CC + lane];
    float sc[CC];
#pragma unroll
    for (int f = 0; f < CC; f++) sc[f] = __shfl_sync(0xffffffffu, score, f);
    if (lane == 0) {
        float best = sc[0];
        int tag = 0;
#pragma unroll
        for (int f = 1; f < CC; f++)
            if (sc[f] > best) { best = sc[f]; tag = f; }
        if (b < osz) out[b] = best;
        long long tb = 64;
        long long o = tb + (long long)b * LL + (LL - 1);
        if (o < osz) out[o] = (float)tag;
        for (int t = LL - 1; t >= 1; t--) {
            tag = bp[((size_t)t * BB + b) * CC + tag];
            o = tb + (long long)b * LL + (t - 1);
            if (o < osz) out[o] = (float)tag;
        }
    }
}

// ---------------- features [t][b][k] -> out [b][t][k] --------------------------
__global__ void feat_out_k(const float* __restrict__ feat, float* __restrict__ out,
                           long long osz)
{
    size_t i = (size_t)blockIdx.x * blockDim.x + threadIdx.x;
    size_t total = (size_t)LL * BB * HID / 4;
    if (i >= total) return;
    int k4 = (int)(i % (HID / 4));
    size_t p = i / (HID / 4);
    int b = (int)(p % BB);
    int t = (int)(p / BB);
    long long o = 32832LL + ((long long)b * LL + t) * HID + k4 * 4;
    if (o + 3 < osz)
        *(float4*)&out[o] = *(const float4*)&feat[p * HID + k4 * 4];
}

__global__ void mask_out_k(float* __restrict__ out, long long osz)
{
    long long i = (long long)blockIdx.x * blockDim.x + threadIdx.x;
    if (i >= (long long)BB * LL) return;
    long long o = 16810048LL + i;
    if (o < osz) out[o] = 1.0f;
}

// ---------------- launch --------------------------------------------------------
extern "C" void kernel_launch(void* const* d_in, const int* in_sizes, int n_in,
                              void* d_out, int out_size)
{
    const int*   xs    = (const int*)  d_in[0];
    const float* emb   = (const float*)d_in[1];
    const float* Wih0  = (const float*)d_in[2];
    const float* Whh0  = (const float*)d_in[3];
    const float* b0    = (const float*)d_in[4];
    const float* WihL  = (const float*)d_in[5];
    const float* WhhL  = (const float*)d_in[6];
    const float* bL    = (const float*)d_in[7];
    const float* Wfc   = (const float*)d_in[8];
    const float* bfc   = (const float*)d_in[9];
    const float* trans = (const float*)d_in[10];
    float* out = (float*)d_out;
    long long osz = out_size;

    float *pX, *pA, *pB, *pG, *pE;
    int* pBP;
    cudaGetSymbolAddress((void**)&pX,  g_embx);
    cudaGetSymbolAddress((void**)&pA,  g_bufA);
    cudaGetSymbolAddress((void**)&pB,  g_bufB);
    cudaGetSymbolAddress((void**)&pG,  g_gates);
    cudaGetSymbolAddress((void**)&pE,  g_emit);
    cudaGetSymbolAddress((void**)&pBP, g_bp);

    cudaFuncSetAttribute(lstm_layer_k, cudaFuncAttributeMaxDynamicSharedMemorySize,
                         LSTM_SMEM);
    cudaFuncSetAttribute(gemm_wmma_k, cudaFuncAttributeMaxDynamicSharedMemorySize,
                         GSM_TOT);

    {
        size_t total = (size_t)LL * BB * (EE / 4);
        embed_k<<<(unsigned)((total + 255) / 256), 256>>>(xs, emb, pX);
    }

    const float* x = pX;
    int K = EE;
    for (int l = 0; l < 4; l++) {
        const float *WihF, *WihB, *WhhF, *WhhB, *bF, *bBk;
        if (l == 0) {
            WihF = Wih0;                 WihB = Wih0 + (size_t)NG * EE;
            WhhF = Whh0;                 WhhB = Whh0 + (size_t)NG * HH;
            bF   = b0;                   bBk  = b0 + NG;
        } else {
            size_t base = (size_t)(l - 1) * 2;
            WihF = WihL + base * NG * HID;       WihB = WihL + (base + 1) * NG * HID;
            WhhF = WhhL + base * NG * HH;        WhhB = WhhL + (base + 1) * NG * HH;
            bF   = bL + base * NG;               bBk  = bL + (base + 1) * NG;
        }
        float* y = (l & 1) ? pB : pA;

        dim3 ggrid(MM / 128, NG / 128, 2);
        gemm_wmma_k<<<ggrid, 256, GSM_TOT>>>(x, WihF, WihB, bF, bBk, pG, K);

        lstm_layer_k<<<32, 256, LSTM_SMEM>>>(pG, WhhF, WhhB, y);

        x = y;
        K = HID;
    }

    fc_k<<<(LL * BB * 32) / 256, 256>>>(x, Wfc, bfc, pE);
    viterbi_k<<<BB, 32>>>(pE, trans, pBP, out, osz);
    {
        size_t total = (size_t)LL * BB * HID / 4;
        feat_out_k<<<(unsigned)((total + 255) / 256), 256>>>(x, out, osz);
    }
    mask_out_k<<<(BB * LL + 255) / 256, 256>>>(out, osz);
}

// round 16
// speedup vs baseline: 1.5800x; 1.0529x over previous
#include <cuda_runtime.h>
#include <math.h>
#include <stdint.h>
#include <mma.h>
#include <cuda_fp16.h>

using namespace nvcuda;

#define LL 512
#define BB 64
#define EE 256
#define HH 256
#define HID 512
#define NG 1024      // 4*H gate rows
#define MM 32768     // LL*BB
#define CC 5
#define TAG_START 3
#define TAG_STOP 4
#define IMPOSSIBLE_F (-1e4f)

typedef unsigned long long ull;

__device__ __forceinline__ float tf32r(float x) {
    uint32_t u; asm("cvt.rna.tf32.f32 %0, %1;" : "=r"(u) : "f"(x));
    return __uint_as_float(u);
}
__device__ __forceinline__ float tanh_a(float x) {
    float r; asm("tanh.approx.f32 %0, %1;" : "=f"(r) : "f"(x)); return r;
}
__device__ __forceinline__ uint32_t smem_u32(const void* p) {
    uint32_t a;
    asm("{ .reg .u64 t; cvta.to.shared.u64 t, %1; cvt.u32.u64 %0, t; }" : "=r"(a) : "l"(p));
    return a;
}
#define CLUSTER_SYNC() do { \
    asm volatile("barrier.cluster.arrive.aligned;" ::: "memory"); \
    asm volatile("barrier.cluster.wait.aligned;" ::: "memory"); \
} while (0)
#define CLUSTER_ARRIVE() \
    asm volatile("barrier.cluster.arrive.aligned;" ::: "memory")
#define CLUSTER_WAIT() \
    asm volatile("barrier.cluster.wait.aligned;" ::: "memory")

// ---------------- scratch (device globals; no cudaMalloc allowed) -------------
__device__ float g_embx [(size_t)LL * BB * EE];
__device__ float g_bufA [(size_t)LL * BB * HID];
__device__ float g_bufB [(size_t)LL * BB * HID];
__device__ float g_gates[(size_t)2 * NG * MM];        // G^T: [dir][n][m]
__device__ float g_emit [(size_t)LL * BB * CC];
__device__ int   g_bp   [(size_t)LL * BB * CC];

// ---------------- embedding gather --------------------------------------------
__global__ void embed_k(const int* __restrict__ xs, const float* __restrict__ emb,
                        float* __restrict__ X)
{
    size_t i = (size_t)blockIdx.x * blockDim.x + threadIdx.x;
    size_t total = (size_t)LL * BB * (EE / 4);
    if (i >= total) return;
    int e4 = (int)(i % (EE / 4));
    size_t p = i / (EE / 4);
    int b = (int)(p % BB);
    int t = (int)(p / BB);
    int tok = xs[(size_t)b * LL + t];
    *(float4*)&X[p * EE + e4 * 4] = *(const float4*)&emb[(size_t)tok * EE + e4 * 4];
}

// ---------------- wmma tf32 input-projection GEMM, transposed output ----------
// GT[dir][n][m] = A[m,:]·W[dir][n,:] + bias[n]   (R14-validated path)
#define GP 36
#define GBUF (128 * GP)
#define BT_STRIDE 132
#define GSM_TOT ((4 * GBUF + 16 * BT_STRIDE) * 4)     // 82176 bytes

__global__ __launch_bounds__(256) void gemm_wmma_k(
    const float* __restrict__ A,
    const float* __restrict__ W0, const float* __restrict__ W1,
    const float* __restrict__ bias0, const float* __restrict__ bias1,
    float* __restrict__ G, int K)
{
    extern __shared__ float sm[];
    float* Abuf[2] = { sm,             sm + GBUF     };
    float* Wbuf[2] = { sm + 2 * GBUF,  sm + 3 * GBUF };
    float* btile   = sm + 4 * GBUF;

    int tid = threadIdx.x, wid = tid >> 5;
    int m0 = blockIdx.x * 128;
    int n0 = blockIdx.y * 128;
    int dir = blockIdx.z;
    const float* W    = dir ? W1 : W0;
    const float* bias = dir ? bias1 : bias0;
    float* Gt = G + (size_t)dir * NG * MM;

    int wm = wid >> 2;
    int wn = wid & 3;

#pragma unroll
    for (int u = 0; u < 8; u++) {
        int idx = tid + u * 256;
        int r = idx >> 7, c = idx & 127;
        btile[r * BT_STRIDE + c] = bias[n0 + c];
    }

    auto stage = [&](int c, int buf) {
        const float* Asrc = A + (size_t)m0 * K + c * 32;
        const float* Wsrc = W + (size_t)n0 * K + c * 32;
        float* ad = Abuf[buf];
        float* wd = Wbuf[buf];
#pragma unroll
        for (int u = 0; u < 4; u++) {
            int idx = tid + u * 256;
            int row = idx >> 3, c4 = idx & 7;
            float4 v = *(const float4*)&Asrc[(size_t)row * K + c4 * 4];
            v.x = tf32r(v.x); v.y = tf32r(v.y); v.z = tf32r(v.z); v.w = tf32r(v.w);
            *(float4*)&ad[row * GP + c4 * 4] = v;
            float4 q = *(const float4*)&Wsrc[(size_t)row * K + c4 * 4];
            q.x = tf32r(q.x); q.y = tf32r(q.y); q.z = tf32r(q.z); q.w = tf32r(q.w);
            *(float4*)&wd[row * GP + c4 * 4] = q;
        }
    };

    stage(0, 0);
    __syncthreads();

    wmma::fragment<wmma::accumulator, 16, 16, 8, float> acc[4][2];
#pragma unroll
    for (int i = 0; i < 4; i++)
#pragma unroll
        for (int j = 0; j < 2; j++)
            wmma::load_matrix_sync(acc[i][j], btile + wn * 32 + j * 16,
                                   BT_STRIDE, wmma::mem_row_major);

    const int NC = K >> 5;
    for (int c = 0; c < NC; c++) {
        int cur = c & 1;
        if (c + 1 < NC) stage(c + 1, cur ^ 1);

        const float* ab = Abuf[cur] + wm * 64 * GP;
        const float* wb = Wbuf[cur] + wn * 32 * GP;
#pragma unroll
        for (int kk = 0; kk < 4; kk++) {
            wmma::fragment<wmma::matrix_a, 16, 16, 8, wmma::precision::tf32,
                           wmma::row_major> af[4];
            wmma::fragment<wmma::matrix_b, 16, 16, 8, wmma::precision::tf32,
                           wmma::col_major> bf[2];
#pragma unroll
            for (int i = 0; i < 4; i++)
                wmma::load_matrix_sync(af[i], ab + i * 16 * GP + kk * 8, GP);
#pragma unroll
            for (int j = 0; j < 2; j++)
                wmma::load_matrix_sync(bf[j], wb + j * 16 * GP + kk * 8, GP);
#pragma unroll
            for (int i = 0; i < 4; i++)
#pragma unroll
                for (int j = 0; j < 2; j++)
                    wmma::mma_sync(acc[i][j], af[i], bf[j], acc[i][j]);
        }
        __syncthreads();
    }

#pragma unroll
    for (int i = 0; i < 4; i++)
#pragma unroll
        for (int j = 0; j < 2; j++) {
            float* gt = Gt + (size_t)(n0 + wn * 32 + j * 16) * MM
                           + (m0 + wm * 64 + i * 16);
            wmma::store_matrix_sync(gt, acc[i][j], MM, wmma::mem_col_major);
        }
}

// ---------------- cluster-local persistent LSTM recurrence ---------------------
// 32 CTAs in 8 clusters of 4. bx: cu = bx&3 (units cu*64..+63),
// cid = bx>>2: dir = cid>>2, bg = cid&3 (batches bg*16..+15). 256 threads.
#define WB_LD 272
#define HA_LD 264
#define CS_LD 260
#define OFF_WB 0
#define OFF_HA0 139264                   // 256*272*2
#define OFF_HA1 (OFF_HA0 + 16 * HA_LD * 2)
#define OFF_CS  (OFF_HA1 + 16 * HA_LD * 2)
#define LSTM_SMEM (OFF_CS + 16 * CS_LD * 4)   // 172800 bytes

__global__ __launch_bounds__(256, 1) __cluster_dims__(4, 1, 1)
void lstm_layer_k(const float* __restrict__ Gt,
                  const float* __restrict__ Whh0, const float* __restrict__ Whh1,
                  float* __restrict__ y)
{
    extern __shared__ char smc[];
    half*  WB  = (half*)(smc + OFF_WB);
    half*  hA[2] = { (half*)(smc + OFF_HA0), (half*)(smc + OFF_HA1) };
    float* Cs  = (float*)(smc + OFF_CS);

    int bx  = blockIdx.x;
    int cu  = bx & 3;
    int cid = bx >> 2;
    int dir = cid >> 2;
    int bg  = cid & 3;
    int tid = threadIdx.x, wid = tid >> 5;
    const float* Whh = dir ? Whh1 : Whh0;
    const float* Gd  = Gt + (size_t)dir * NG * MM;

    // ---- load weight slice fp32->fp16: WB[k][n_l], n_l = g*64+u -------------
#pragma unroll 4
    for (int it = 0; it < 64; it++) {
        int flat = tid + it * 256;
        int n_l = flat >> 6, k4 = flat & 63;
        int g = n_l >> 6, u = n_l & 63;
        float4 v = *(const float4*)&Whh[(size_t)(g * 256 + cu * 64 + u) * HH + k4 * 4];
        WB[(k4 * 4 + 0) * WB_LD + n_l] = __float2half_rn(v.x);
        WB[(k4 * 4 + 1) * WB_LD + n_l] = __float2half_rn(v.y);
        WB[(k4 * 4 + 2) * WB_LD + n_l] = __float2half_rn(v.z);
        WB[(k4 * 4 + 3) * WB_LD + n_l] = __float2half_rn(v.w);
    }

    int b  = tid & 15;
    int ug = tid >> 4;
    float cst[4] = {0.f, 0.f, 0.f, 0.f};

    uint32_t habase[2] = { smem_u32(hA[0]), smem_u32(hA[1]) };

    __syncthreads();
    CLUSTER_SYNC();                      // weights staged cluster-wide

    float gpre[16];
    {
        int t0 = dir ? (LL - 1) : 0;
#pragma unroll
        for (int g = 0; g < 4; g++)
#pragma unroll
            for (int i = 0; i < 4; i++)
                gpre[g * 4 + i] =
                    Gd[(size_t)(g * 256 + cu * 64 + ug * 4 + i) * MM
                       + (size_t)t0 * 64 + bg * 16 + b];
    }

    for (int s = 0; s < LL; s++) {
        int t = dir ? (LL - 1 - s) : s;

        if (s > 0) {
            // software-pipelined fp16 wmma: warp w owns n in [w*32, w*32+32)
            const half* ha = hA[s & 1];
            const half* wb0 = WB + wid * 32;
            wmma::fragment<wmma::accumulator, 16, 16, 16, float> acc0, acc1;
            wmma::fill_fragment(acc0, 0.f);
            wmma::fill_fragment(acc1, 0.f);
            wmma::fragment<wmma::matrix_a, 16, 16, 16, half,
                           wmma::row_major> af[2];
            wmma::fragment<wmma::matrix_b, 16, 16, 16, half,
                           wmma::row_major> bf0[2], bf1[2];
            wmma::load_matrix_sync(af[0], ha, HA_LD);
            wmma::load_matrix_sync(bf0[0], wb0, WB_LD);
            wmma::load_matrix_sync(bf1[0], wb0 + 16, WB_LD);
#pragma unroll
            for (int kf = 0; kf < 16; kf++) {
                int cur = kf & 1, nxt = cur ^ 1;
                if (kf < 15) {
                    wmma::load_matrix_sync(af[nxt], ha + (kf + 1) * 16, HA_LD);
                    wmma::load_matrix_sync(bf0[nxt],
                        wb0 + ((kf + 1) * 16) * WB_LD, WB_LD);
                    wmma::load_matrix_sync(bf1[nxt],
                        wb0 + ((kf + 1) * 16) * WB_LD + 16, WB_LD);
                }
                wmma::mma_sync(acc0, af[cur], bf0[cur], acc0);
                wmma::mma_sync(acc1, af[cur], bf1[cur], acc1);
            }
            wmma::store_matrix_sync(Cs + wid * 32,      acc0, CS_LD,
                                    wmma::mem_row_major);
            wmma::store_matrix_sync(Cs + wid * 32 + 16, acc1, CS_LD,
                                    wmma::mem_row_major);
        }
        __syncthreads();                 // Cs ready

        float hv[4];
#pragma unroll
        for (int i = 0; i < 4; i++) {
            float pi = gpre[0 * 4 + i];
            float pf = gpre[1 * 4 + i];
            float pg = gpre[2 * 4 + i];
            float po = gpre[3 * 4 + i];
            if (s > 0) {
                const float* cb = Cs + b * CS_LD + ug * 4 + i;
                pi += cb[0 * 64];
                pf += cb[1 * 64];
                pg += cb[2 * 64];
                po += cb[3 * 64];
            }
            float ig = 0.5f * (1.f + tanh_a(0.5f * pi));
            float fg = 0.5f * (1.f + tanh_a(0.5f * pf));
            float gg = tanh_a(pg);
            float og = 0.5f * (1.f + tanh_a(0.5f * po));
            cst[i] = fg * cst[i] + ig * gg;
            hv[i] = og * tanh_a(cst[i]);
        }

        if (s + 1 < LL) {
            // publish h slice to all 4 cluster CTAs (fp16)
            uint32_t hdst = habase[(s + 1) & 1]
                          + (uint32_t)(b * HA_LD + cu * 64 + ug * 4) * 2;
            half2 p0 = __halves2half2(__float2half_rn(hv[0]), __float2half_rn(hv[1]));
            half2 p1 = __halves2half2(__float2half_rn(hv[2]), __float2half_rn(hv[3]));
            uint32_t u0 = *(uint32_t*)&p0;
            uint32_t u1 = *(uint32_t*)&p1;
#pragma unroll
            for (int r = 0; r < 4; r++) {
                uint32_t ra;
                asm volatile("mapa.shared::cluster.u32 %0, %1, %2;"
                             : "=r"(ra) : "r"(hdst), "r"(r));
                asm volatile("st.shared::cluster.u32 [%0], %1;"
                             :: "r"(ra), "r"(u0) : "memory");
                asm volatile("st.shared::cluster.u32 [%0], %1;"
                             :: "r"(ra + 4), "r"(u1) : "memory");
            }
            CLUSTER_ARRIVE();            // release stores; overlap skew below

            // y writeout (independent of barrier)
            float4 v = make_float4(hv[0], hv[1], hv[2], hv[3]);
            *(float4*)&y[((size_t)t * BB + bg * 16 + b) * HID
                         + dir * HH + cu * 64 + ug * 4] = v;

            // prefetch G for next step (gmem latency hides behind wait)
            int tn = dir ? (LL - 2 - s) : (s + 1);
#pragma unroll
            for (int g = 0; g < 4; g++)
#pragma unroll
                for (int i = 0; i < 4; i++)
                    gpre[g * 4 + i] =
                        Gd[(size_t)(g * 256 + cu * 64 + ug * 4 + i) * MM
                           + (size_t)tn * 64 + bg * 16 + b];

            CLUSTER_WAIT();              // h published cluster-wide
        } else {
            // last step: no publish needed, just write y
            float4 v = make_float4(hv[0], hv[1], hv[2], hv[3]);
            *(float4*)&y[((size_t)t * BB + bg * 16 + b) * HID
                         + dir * HH + cu * 64 + ug * 4] = v;
        }
    }
}

// ---------------- FC -----------------------------------------------------------
__global__ void fc_k(const float* __restrict__ feat, const float* __restrict__ Wfc,
                     const float* __restrict__ bfc, float* __restrict__ emit)
{
    int gw = (int)(((size_t)blockIdx.x * blockDim.x + threadIdx.x) >> 5);
    int lane = threadIdx.x & 31;
    if (gw >= LL * BB) return;
    const float* f = feat + (size_t)gw * HID;
    float acc[CC] = {0.f, 0.f, 0.f, 0.f, 0.f};
#pragma unroll
    for (int i = 0; i < HID / 32; i++) {
        int k = lane + i * 32;
        float fv = f[k];
#pragma unroll
        for (int cc = 0; cc < CC; cc++) acc[cc] += fv * Wfc[cc * HID + k];
    }
#pragma unroll
    for (int off = 16; off > 0; off >>= 1)
#pragma unroll
        for (int cc = 0; cc < CC; cc++)
            acc[cc] += __shfl_down_sync(0xffffffffu, acc[cc], off);
    if (lane == 0)
#pragma unroll
        for (int cc = 0; cc < CC; cc++)
            emit[(size_t)gw * CC + cc] = acc[cc] + bfc[cc];
}

// ---------------- Viterbi + backtrace ------------------------------------------
__global__ void viterbi_k(const float* __restrict__ emit, const float* __restrict__ trans,
                          int* __restrict__ bp, float* __restrict__ out, long long osz)
{
    int b = blockIdx.x;
    int lane = threadIdx.x;
    float tr[CC];
    if (lane < CC)
#pragma unroll
        for (int f = 0; f < CC; f++) tr[f] = trans[lane * CC + f];
    float score = (lane == TAG_START) ? 0.f : IMPOSSIBLE_F;

    for (int t = 0; t < LL; t++) {
        float sc[CC];
#pragma unroll
        for (int f = 0; f < CC; f++) sc[f] = __shfl_sync(0xffffffffu, score, f);
        if (lane < CC) {
            float best = sc[0] + tr[0];
            int arg = 0;
#pragma unroll
            for (int f = 1; f < CC; f++) {
                float v = sc[f] + tr[f];
                if (v > best) { best = v; arg = f; }
            }
            bp[((size_t)t * BB + b) * CC + lane] = arg;
            score = best + emit[((size_t)t * BB + b) * CC + lane];
        }
    }
    if (lane < CC) score += trans[TAG_STOP * CC + lane];
    float sc[CC];
#pragma unroll
    for (int f = 0; f < CC; f++) sc[f] = __shfl_sync(0xffffffffu, score, f);
    if (lane == 0) {
        float best = sc[0];
        int tag = 0;
#pragma unroll
        for (int f = 1; f < CC; f++)
            if (sc[f] > best) { best = sc[f]; tag = f; }
        if (b < osz) out[b] = best;
        long long tb = 64;
        long long o = tb + (long long)b * LL + (LL - 1);
        if (o < osz) out[o] = (float)tag;
        for (int t = LL - 1; t >= 1; t--) {
            tag = bp[((size_t)t * BB + b) * CC + tag];
            o = tb + (long long)b * LL + (t - 1);
            if (o < osz) out[o] = (float)tag;
        }
    }
}

// ---------------- features [t][b][k] -> out [b][t][k] --------------------------
__global__ void feat_out_k(const float* __restrict__ feat, float* __restrict__ out,
                           long long osz)
{
    size_t i = (size_t)blockIdx.x * blockDim.x + threadIdx.x;
    size_t total = (size_t)LL * BB * HID / 4;
    if (i >= total) return;
    int k4 = (int)(i % (HID / 4));
    size_t p = i / (HID / 4);
    int b = (int)(p % BB);
    int t = (int)(p / BB);
    long long o = 32832LL + ((long long)b * LL + t) * HID + k4 * 4;
    if (o + 3 < osz)
        *(float4*)&out[o] = *(const float4*)&feat[p * HID + k4 * 4];
}

__global__ void mask_out_k(float* __restrict__ out, long long osz)
{
    long long i = (long long)blockIdx.x * blockDim.x + threadIdx.x;
    if (i >= (long long)BB * LL) return;
    long long o = 16810048LL + i;
    if (o < osz) out[o] = 1.0f;
}

// ---------------- launch --------------------------------------------------------
extern "C" void kernel_launch(void* const* d_in, const int* in_sizes, int n_in,
                              void* d_out, int out_size)
{
    const int*   xs    = (const int*)  d_in[0];
    const float* emb   = (const float*)d_in[1];
    const float* Wih0  = (const float*)d_in[2];
    const float* Whh0  = (const float*)d_in[3];
    const float* b0    = (const float*)d_in[4];
    const float* WihL  = (const float*)d_in[5];
    const float* WhhL  = (const float*)d_in[6];
    const float* bL    = (const float*)d_in[7];
    const float* Wfc   = (const float*)d_in[8];
    const float* bfc   = (const float*)d_in[9];
    const float* trans = (const float*)d_in[10];
    float* out = (float*)d_out;
    long long osz = out_size;

    float *pX, *pA, *pB, *pG, *pE;
    int* pBP;
    cudaGetSymbolAddress((void**)&pX,  g_embx);
    cudaGetSymbolAddress((void**)&pA,  g_bufA);
    cudaGetSymbolAddress((void**)&pB,  g_bufB);
    cudaGetSymbolAddress((void**)&pG,  g_gates);
    cudaGetSymbolAddress((void**)&pE,  g_emit);
    cudaGetSymbolAddress((void**)&pBP, g_bp);

    cudaFuncSetAttribute(lstm_layer_k, cudaFuncAttributeMaxDynamicSharedMemorySize,
                         LSTM_SMEM);
    cudaFuncSetAttribute(gemm_wmma_k, cudaFuncAttributeMaxDynamicSharedMemorySize,
                         GSM_TOT);

    {
        size_t total = (size_t)LL * BB * (EE / 4);
        embed_k<<<(unsigned)((total + 255) / 256), 256>>>(xs, emb, pX);
    }

    const float* x = pX;
    int K = EE;
    for (int l = 0; l < 4; l++) {
        const float *WihF, *WihB, *WhhF, *WhhB, *bF, *bBk;
        if (l == 0) {
            WihF = Wih0;                 WihB = Wih0 + (size_t)NG * EE;
            WhhF = Whh0;                 WhhB = Whh0 + (size_t)NG * HH;
            bF   = b0;                   bBk  = b0 + NG;
        } else {
            size_t base = (size_t)(l - 1) * 2;
            WihF = WihL + base * NG * HID;       WihB = WihL + (base + 1) * NG * HID;
            WhhF = WhhL + base * NG * HH;        WhhB = WhhL + (base + 1) * NG * HH;
            bF   = bL + base * NG;               bBk  = bL + (base + 1) * NG;
        }
        float* y = (l & 1) ? pB : pA;

        dim3 ggrid(MM / 128, NG / 128, 2);
        gemm_wmma_k<<<ggrid, 256, GSM_TOT>>>(x, WihF, WihB, bF, bBk, pG, K);

        lstm_layer_k<<<32, 256, LSTM_SMEM>>>(pG, WhhF, WhhB, y);

        x = y;
        K = HID;
    }

    fc_k<<<(LL * BB * 32) / 256, 256>>>(x, Wfc, bfc, pE);
    viterbi_k<<<BB, 32>>>(pE, trans, pBP, out, osz);
    {
        size_t total = (size_t)LL * BB * HID / 4;
        feat_out_k<<<(unsigned)((total + 255) / 256), 256>>>(x, out, osz);
    }
    mask_out_k<<<(BB * LL + 255) / 256, 256>>>(out, osz);
}

// round 17
// speedup vs baseline: 1.6501x; 1.0444x over previous
#include <cuda_runtime.h>
#include <math.h>
#include <stdint.h>
#include <mma.h>
#include <cuda_fp16.h>

using namespace nvcuda;

#define LL 512
#define BB 64
#define EE 256
#define HH 256
#define HID 512
#define NG 1024      // 4*H gate rows
#define MM 32768     // LL*BB
#define CC 5
#define TAG_START 3
#define TAG_STOP 4
#define IMPOSSIBLE_F (-1e4f)

typedef unsigned long long ull;

__device__ __forceinline__ float tf32r(float x) {
    uint32_t u; asm("cvt.rna.tf32.f32 %0, %1;" : "=r"(u) : "f"(x));
    return __uint_as_float(u);
}
__device__ __forceinline__ float tanh_a(float x) {
    float r; asm("tanh.approx.f32 %0, %1;" : "=f"(r) : "f"(x)); return r;
}
__device__ __forceinline__ uint32_t smem_u32(const void* p) {
    uint32_t a;
    asm("{ .reg .u64 t; cvta.to.shared.u64 t, %1; cvt.u32.u64 %0, t; }" : "=r"(a) : "l"(p));
    return a;
}
#define CLUSTER_SYNC() do { \
    asm volatile("barrier.cluster.arrive.aligned;" ::: "memory"); \
    asm volatile("barrier.cluster.wait.aligned;" ::: "memory"); \
} while (0)
#define CLUSTER_ARRIVE() \
    asm volatile("barrier.cluster.arrive.aligned;" ::: "memory")
#define CLUSTER_WAIT() \
    asm volatile("barrier.cluster.wait.aligned;" ::: "memory")

// ---------------- scratch (device globals; no cudaMalloc allowed) -------------
__device__ float g_embx [(size_t)LL * BB * EE];
__device__ float g_bufA [(size_t)LL * BB * HID];
__device__ float g_bufB [(size_t)LL * BB * HID];
__device__ float g_gates[(size_t)2 * NG * MM];        // G^T: [dir][n][m]
__device__ float g_emit [(size_t)LL * BB * CC];
__device__ int   g_bp   [(size_t)LL * BB * CC];

// ---------------- embedding gather --------------------------------------------
__global__ void embed_k(const int* __restrict__ xs, const float* __restrict__ emb,
                        float* __restrict__ X)
{
    size_t i = (size_t)blockIdx.x * blockDim.x + threadIdx.x;
    size_t total = (size_t)LL * BB * (EE / 4);
    if (i >= total) return;
    int e4 = (int)(i % (EE / 4));
    size_t p = i / (EE / 4);
    int b = (int)(p % BB);
    int t = (int)(p / BB);
    int tok = xs[(size_t)b * LL + t];
    *(float4*)&X[p * EE + e4 * 4] = *(const float4*)&emb[(size_t)tok * EE + e4 * 4];
}

// ---------------- wmma tf32 input-projection GEMM, transposed output ----------
// GT[dir][n][m] = A[m,:]·W[dir][n,:] + bias[n]
// Staging split: LDG->regs prefetch during mma, cvt+STS after.
#define GP 36
#define GBUF (128 * GP)
#define BT_STRIDE 132
#define GSM_TOT ((4 * GBUF + 16 * BT_STRIDE) * 4)     // 82176 bytes

__global__ __launch_bounds__(256) void gemm_wmma_k(
    const float* __restrict__ A,
    const float* __restrict__ W0, const float* __restrict__ W1,
    const float* __restrict__ bias0, const float* __restrict__ bias1,
    float* __restrict__ G, int K)
{
    extern __shared__ float sm[];
    float* Abuf[2] = { sm,             sm + GBUF     };
    float* Wbuf[2] = { sm + 2 * GBUF,  sm + 3 * GBUF };
    float* btile   = sm + 4 * GBUF;

    int tid = threadIdx.x, wid = tid >> 5;
    int m0 = blockIdx.x * 128;
    int n0 = blockIdx.y * 128;
    int dir = blockIdx.z;
    const float* W    = dir ? W1 : W0;
    const float* bias = dir ? bias1 : bias0;
    float* Gt = G + (size_t)dir * NG * MM;

    int wm = wid >> 2;
    int wn = wid & 3;

#pragma unroll
    for (int u = 0; u < 8; u++) {
        int idx = tid + u * 256;
        int r = idx >> 7, c = idx & 127;
        btile[r * BT_STRIDE + c] = bias[n0 + c];
    }

    // per-thread staging coords
    int srow[4], sc4[4];
#pragma unroll
    for (int u = 0; u < 4; u++) {
        int idx = tid + u * 256;
        srow[u] = idx >> 3; sc4[u] = idx & 7;
    }

    float4 aR[4], wR[4];
    auto ldg = [&](int c) {
        const float* Asrc = A + (size_t)m0 * K + c * 32;
        const float* Wsrc = W + (size_t)n0 * K + c * 32;
#pragma unroll
        for (int u = 0; u < 4; u++) {
            aR[u] = *(const float4*)&Asrc[(size_t)srow[u] * K + sc4[u] * 4];
            wR[u] = *(const float4*)&Wsrc[(size_t)srow[u] * K + sc4[u] * 4];
        }
    };
    auto sts = [&](int buf) {
        float* ad = Abuf[buf];
        float* wd = Wbuf[buf];
#pragma unroll
        for (int u = 0; u < 4; u++) {
            float4 v = aR[u];
            v.x = tf32r(v.x); v.y = tf32r(v.y); v.z = tf32r(v.z); v.w = tf32r(v.w);
            *(float4*)&ad[srow[u] * GP + sc4[u] * 4] = v;
            float4 q = wR[u];
            q.x = tf32r(q.x); q.y = tf32r(q.y); q.z = tf32r(q.z); q.w = tf32r(q.w);
            *(float4*)&wd[srow[u] * GP + sc4[u] * 4] = q;
        }
    };

    ldg(0); sts(0);
    __syncthreads();

    wmma::fragment<wmma::accumulator, 16, 16, 8, float> acc[4][2];
#pragma unroll
    for (int i = 0; i < 4; i++)
#pragma unroll
        for (int j = 0; j < 2; j++)
            wmma::load_matrix_sync(acc[i][j], btile + wn * 32 + j * 16,
                                   BT_STRIDE, wmma::mem_row_major);

    const int NC = K >> 5;
    for (int c = 0; c < NC; c++) {
        int cur = c & 1;
        bool more = (c + 1 < NC);
        if (more) ldg(c + 1);            // LDG in flight during mma below

        const float* ab = Abuf[cur] + wm * 64 * GP;
        const float* wb = Wbuf[cur] + wn * 32 * GP;
#pragma unroll
        for (int kk = 0; kk < 4; kk++) {
            wmma::fragment<wmma::matrix_a, 16, 16, 8, wmma::precision::tf32,
                           wmma::row_major> af[4];
            wmma::fragment<wmma::matrix_b, 16, 16, 8, wmma::precision::tf32,
                           wmma::col_major> bf[2];
#pragma unroll
            for (int i = 0; i < 4; i++)
                wmma::load_matrix_sync(af[i], ab + i * 16 * GP + kk * 8, GP);
#pragma unroll
            for (int j = 0; j < 2; j++)
                wmma::load_matrix_sync(bf[j], wb + j * 16 * GP + kk * 8, GP);
#pragma unroll
            for (int i = 0; i < 4; i++)
#pragma unroll
                for (int j = 0; j < 2; j++)
                    wmma::mma_sync(acc[i][j], af[i], bf[j], acc[i][j]);
        }
        if (more) sts(cur ^ 1);          // STS after mma (loads have landed)
        __syncthreads();
    }

#pragma unroll
    for (int i = 0; i < 4; i++)
#pragma unroll
        for (int j = 0; j < 2; j++) {
            float* gt = Gt + (size_t)(n0 + wn * 32 + j * 16) * MM
                           + (m0 + wm * 64 + i * 16);
            wmma::store_matrix_sync(gt, acc[i][j], MM, wmma::mem_col_major);
        }
}

// ---------------- cluster-local persistent LSTM recurrence ---------------------
// 32 CTAs in 8 clusters of 4. bx: cu = bx&3 (units cu*64..+63),
// cid = bx>>2: dir = cid>>2, bg = cid&3 (batches bg*16..+15). 256 threads.
#define WB_LD 272
#define HA_LD 264
#define CS_LD 260
#define OFF_WB 0
#define OFF_HA0 139264                   // 256*272*2
#define OFF_HA1 (OFF_HA0 + 16 * HA_LD * 2)
#define OFF_CS  (OFF_HA1 + 16 * HA_LD * 2)
#define LSTM_SMEM (OFF_CS + 16 * CS_LD * 4)   // 172800 bytes

__global__ __launch_bounds__(256, 1) __cluster_dims__(4, 1, 1)
void lstm_layer_k(const float* __restrict__ Gt,
                  const float* __restrict__ Whh0, const float* __restrict__ Whh1,
                  float* __restrict__ y)
{
    extern __shared__ char smc[];
    half*  WB  = (half*)(smc + OFF_WB);
    half*  hA[2] = { (half*)(smc + OFF_HA0), (half*)(smc + OFF_HA1) };
    float* Cs  = (float*)(smc + OFF_CS);

    int bx  = blockIdx.x;
    int cu  = bx & 3;
    int cid = bx >> 2;
    int dir = cid >> 2;
    int bg  = cid & 3;
    int tid = threadIdx.x, wid = tid >> 5;
    const float* Whh = dir ? Whh1 : Whh0;
    const float* Gd  = Gt + (size_t)dir * NG * MM;

    // ---- load weight slice fp32->fp16: WB[k][n_l], n_l = g*64+u -------------
#pragma unroll 4
    for (int it = 0; it < 64; it++) {
        int flat = tid + it * 256;
        int n_l = flat >> 6, k4 = flat & 63;
        int g = n_l >> 6, u = n_l & 63;
        float4 v = *(const float4*)&Whh[(size_t)(g * 256 + cu * 64 + u) * HH + k4 * 4];
        WB[(k4 * 4 + 0) * WB_LD + n_l] = __float2half_rn(v.x);
        WB[(k4 * 4 + 1) * WB_LD + n_l] = __float2half_rn(v.y);
        WB[(k4 * 4 + 2) * WB_LD + n_l] = __float2half_rn(v.z);
        WB[(k4 * 4 + 3) * WB_LD + n_l] = __float2half_rn(v.w);
    }

    int b  = tid & 15;
    int ug = tid >> 4;
    float cst[4] = {0.f, 0.f, 0.f, 0.f};

    uint32_t habase[2] = { smem_u32(hA[0]), smem_u32(hA[1]) };

    __syncthreads();
    CLUSTER_SYNC();                      // weights staged cluster-wide

    float gpre[16];
    {
        int t0 = dir ? (LL - 1) : 0;
#pragma unroll
        for (int g = 0; g < 4; g++)
#pragma unroll
            for (int i = 0; i < 4; i++)
                gpre[g * 4 + i] =
                    Gd[(size_t)(g * 256 + cu * 64 + ug * 4 + i) * MM
                       + (size_t)t0 * 64 + bg * 16 + b];
    }

    for (int s = 0; s < LL; s++) {
        int t = dir ? (LL - 1 - s) : s;

        if (s > 0) {
            // software-pipelined fp16 wmma: warp w owns n in [w*32, w*32+32)
            const half* ha = hA[s & 1];
            const half* wb0 = WB + wid * 32;
            wmma::fragment<wmma::accumulator, 16, 16, 16, float> acc0, acc1;
            wmma::fill_fragment(acc0, 0.f);
            wmma::fill_fragment(acc1, 0.f);
            wmma::fragment<wmma::matrix_a, 16, 16, 16, half,
                           wmma::row_major> af[2];
            wmma::fragment<wmma::matrix_b, 16, 16, 16, half,
                           wmma::row_major> bf0[2], bf1[2];
            wmma::load_matrix_sync(af[0], ha, HA_LD);
            wmma::load_matrix_sync(bf0[0], wb0, WB_LD);
            wmma::load_matrix_sync(bf1[0], wb0 + 16, WB_LD);
#pragma unroll
            for (int kf = 0; kf < 16; kf++) {
                int cur = kf & 1, nxt = cur ^ 1;
                if (kf < 15) {
                    wmma::load_matrix_sync(af[nxt], ha + (kf + 1) * 16, HA_LD);
                    wmma::load_matrix_sync(bf0[nxt],
                        wb0 + ((kf + 1) * 16) * WB_LD, WB_LD);
                    wmma::load_matrix_sync(bf1[nxt],
                        wb0 + ((kf + 1) * 16) * WB_LD + 16, WB_LD);
                }
                wmma::mma_sync(acc0, af[cur], bf0[cur], acc0);
                wmma::mma_sync(acc1, af[cur], bf1[cur], acc1);
            }
            wmma::store_matrix_sync(Cs + wid * 32,      acc0, CS_LD,
                                    wmma::mem_row_major);
            wmma::store_matrix_sync(Cs + wid * 32 + 16, acc1, CS_LD,
                                    wmma::mem_row_major);
        }
        __syncthreads();                 // Cs ready

        float hv[4];
#pragma unroll
        for (int i = 0; i < 4; i++) {
            float pi = gpre[0 * 4 + i];
            float pf = gpre[1 * 4 + i];
            float pg = gpre[2 * 4 + i];
            float po = gpre[3 * 4 + i];
            if (s > 0) {
                const float* cb = Cs + b * CS_LD + ug * 4 + i;
                pi += cb[0 * 64];
                pf += cb[1 * 64];
                pg += cb[2 * 64];
                po += cb[3 * 64];
            }
            float ig = 0.5f * (1.f + tanh_a(0.5f * pi));
            float fg = 0.5f * (1.f + tanh_a(0.5f * pf));
            float gg = tanh_a(pg);
            float og = 0.5f * (1.f + tanh_a(0.5f * po));
            cst[i] = fg * cst[i] + ig * gg;
            hv[i] = og * tanh_a(cst[i]);
        }

        if (s + 1 < LL) {
            // publish h slice to all 4 cluster CTAs (fp16, one u64 per rank)
            uint32_t hdst = habase[(s + 1) & 1]
                          + (uint32_t)(b * HA_LD + cu * 64 + ug * 4) * 2;
            half2 p0 = __halves2half2(__float2half_rn(hv[0]), __float2half_rn(hv[1]));
            half2 p1 = __halves2half2(__float2half_rn(hv[2]), __float2half_rn(hv[3]));
            uint32_t u0 = *(uint32_t*)&p0;
            uint32_t u1 = *(uint32_t*)&p1;
            ull pk = ((ull)u1 << 32) | (ull)u0;
#pragma unroll
            for (int r = 0; r < 4; r++) {
                uint32_t ra;
                asm volatile("mapa.shared::cluster.u32 %0, %1, %2;"
                             : "=r"(ra) : "r"(hdst), "r"(r));
                asm volatile("st.shared::cluster.u64 [%0], %1;"
                             :: "r"(ra), "l"(pk) : "memory");
            }
            CLUSTER_ARRIVE();            // release stores; overlap skew below

            // y writeout (independent of barrier)
            float4 v = make_float4(hv[0], hv[1], hv[2], hv[3]);
            *(float4*)&y[((size_t)t * BB + bg * 16 + b) * HID
                         + dir * HH + cu * 64 + ug * 4] = v;

            // prefetch G for next step (gmem latency hides behind wait)
            int tn = dir ? (LL - 2 - s) : (s + 1);
#pragma unroll
            for (int g = 0; g < 4; g++)
#pragma unroll
                for (int i = 0; i < 4; i++)
                    gpre[g * 4 + i] =
                        Gd[(size_t)(g * 256 + cu * 64 + ug * 4 + i) * MM
                           + (size_t)tn * 64 + bg * 16 + b];

            CLUSTER_WAIT();              // h published cluster-wide
        } else {
            float4 v = make_float4(hv[0], hv[1], hv[2], hv[3]);
            *(float4*)&y[((size_t)t * BB + bg * 16 + b) * HID
                         + dir * HH + cu * 64 + ug * 4] = v;
        }
    }
}

// ---------------- FC -----------------------------------------------------------
__global__ void fc_k(const float* __restrict__ feat, const float* __restrict__ Wfc,
                     const float* __restrict__ bfc, float* __restrict__ emit)
{
    int gw = (int)(((size_t)blockIdx.x * blockDim.x + threadIdx.x) >> 5);
    int lane = threadIdx.x & 31;
    if (gw >= LL * BB) return;
    const float* f = feat + (size_t)gw * HID;
    float acc[CC] = {0.f, 0.f, 0.f, 0.f, 0.f};
#pragma unroll
    for (int i = 0; i < HID / 32; i++) {
        int k = lane + i * 32;
        float fv = f[k];
#pragma unroll
        for (int cc = 0; cc < CC; cc++) acc[cc] += fv * Wfc[cc * HID + k];
    }
#pragma unroll
    for (int off = 16; off > 0; off >>= 1)
#pragma unroll
        for (int cc = 0; cc < CC; cc++)
            acc[cc] += __shfl_down_sync(0xffffffffu, acc[cc], off);
    if (lane == 0)
#pragma unroll
        for (int cc = 0; cc < CC; cc++)
            emit[(size_t)gw * CC + cc] = acc[cc] + bfc[cc];
}

// ---------------- Viterbi + backtrace ------------------------------------------
__global__ void viterbi_k(const float* __restrict__ emit, const float* __restrict__ trans,
                          int* __restrict__ bp, float* __restrict__ out, long long osz)
{
    int b = blockIdx.x;
    int lane = threadIdx.x;
    float tr[CC];
    if (lane < CC)
#pragma unroll
        for (int f = 0; f < CC; f++) tr[f] = trans[lane * CC + f];
    float score = (lane == TAG_START) ? 0.f : IMPOSSIBLE_F;

    for (int t = 0; t < LL; t++) {
        float sc[CC];
#pragma unroll
        for (int f = 0; f < CC; f++) sc[f] = __shfl_sync(0xffffffffu, score, f);
        if (lane < CC) {
            float best = sc[0] + tr[0];
            int arg = 0;
#pragma unroll
            for (int f = 1; f < CC; f++) {
                float v = sc[f] + tr[f];
                if (v > best) { best = v; arg = f; }
            }
            bp[((size_t)t * BB + b) * CC + lane] = arg;
            score = best + emit[((size_t)t * BB + b) * CC + lane];
        }
    }
    if (lane < CC) score += trans[TAG_STOP * CC + lane];
    float sc[CC];
#pragma unroll
    for (int f = 0; f < CC; f++) sc[f] = __shfl_sync(0xffffffffu, score, f);
    if (lane == 0) {
        float best = sc[0];
        int tag = 0;
#pragma unroll
        for (int f = 1; f < CC; f++)
            if (sc[f] > best) { best = sc[f]; tag = f; }
        if (b < osz) out[b] = best;
        long long tb = 64;
        long long o = tb + (long long)b * LL + (LL - 1);
        if (o < osz) out[o] = (float)tag;
        for (int t = LL - 1; t >= 1; t--) {
            tag = bp[((size_t)t * BB + b) * CC + tag];
            o = tb + (long long)b * LL + (t - 1);
            if (o < osz) out[o] = (float)tag;
        }
    }
}

// ---------------- features [t][b][k] -> out [b][t][k] --------------------------
__global__ void feat_out_k(const float* __restrict__ feat, float* __restrict__ out,
                           long long osz)
{
    size_t i = (size_t)blockIdx.x * blockDim.x + threadIdx.x;
    size_t total = (size_t)LL * BB * HID / 4;
    if (i >= total) return;
    int k4 = (int)(i % (HID / 4));
    size_t p = i / (HID / 4);
    int b = (int)(p % BB);
    int t = (int)(p / BB);
    long long o = 32832LL + ((long long)b * LL + t) * HID + k4 * 4;
    if (o + 3 < osz)
        *(float4*)&out[o] = *(const float4*)&feat[p * HID + k4 * 4];
}

__global__ void mask_out_k(float* __restrict__ out, long long osz)
{
    long long i = (long long)blockIdx.x * blockDim.x + threadIdx.x;
    if (i >= (long long)BB * LL) return;
    long long o = 16810048LL + i;
    if (o < osz) out[o] = 1.0f;
}

// ---------------- launch --------------------------------------------------------
extern "C" void kernel_launch(void* const* d_in, const int* in_sizes, int n_in,
                              void* d_out, int out_size)
{
    const int*   xs    = (const int*)  d_in[0];
    const float* emb   = (const float*)d_in[1];
    const float* Wih0  = (const float*)d_in[2];
    const float* Whh0  = (const float*)d_in[3];
    const float* b0    = (const float*)d_in[4];
    const float* WihL  = (const float*)d_in[5];
    const float* WhhL  = (const float*)d_in[6];
    const float* bL    = (const float*)d_in[7];
    const float* Wfc   = (const float*)d_in[8];
    const float* bfc   = (const float*)d_in[9];
    const float* trans = (const float*)d_in[10];
    float* out = (float*)d_out;
    long long osz = out_size;

    float *pX, *pA, *pB, *pG, *pE;
    int* pBP;
    cudaGetSymbolAddress((void**)&pX,  g_embx);
    cudaGetSymbolAddress((void**)&pA,  g_bufA);
    cudaGetSymbolAddress((void**)&pB,  g_bufB);
    cudaGetSymbolAddress((void**)&pG,  g_gates);
    cudaGetSymbolAddress((void**)&pE,  g_emit);
    cudaGetSymbolAddress((void**)&pBP, g_bp);

    cudaFuncSetAttribute(lstm_layer_k, cudaFuncAttributeMaxDynamicSharedMemorySize,
                         LSTM_SMEM);
    cudaFuncSetAttribute(gemm_wmma_k, cudaFuncAttributeMaxDynamicSharedMemorySize,
                         GSM_TOT);

    {
        size_t total = (size_t)LL * BB * (EE / 4);
        embed_k<<<(unsigned)((total + 255) / 256), 256>>>(xs, emb, pX);
    }

    const float* x = pX;
    int K = EE;
    for (int l = 0; l < 4; l++) {
        const float *WihF, *WihB, *WhhF, *WhhB, *bF, *bBk;
        if (l == 0) {
            WihF = Wih0;                 WihB = Wih0 + (size_t)NG * EE;
            WhhF = Whh0;                 WhhB = Whh0 + (size_t)NG * HH;
            bF   = b0;                   bBk  = b0 + NG;
        } else {
            size_t base = (size_t)(l - 1) * 2;
            WihF = WihL + base * NG * HID;       WihB = WihL + (base + 1) * NG * HID;
            WhhF = WhhL + base * NG * HH;        WhhB = WhhL + (base + 1) * NG * HH;
            bF   = bL + base * NG;               bBk  = bL + (base + 1) * NG;
        }
        float* y = (l & 1) ? pB : pA;

        dim3 ggrid(MM / 128, NG / 128, 2);
        gemm_wmma_k<<<ggrid, 256, GSM_TOT>>>(x, WihF, WihB, bF, bBk, pG, K);

        lstm_layer_k<<<32, 256, LSTM_SMEM>>>(pG, WhhF, WhhB, y);

        x = y;
        K = HID;
    }

    fc_k<<<(LL * BB * 32) / 256, 256>>>(x, Wfc, bfc, pE);
    viterbi_k<<<BB, 32>>>(pE, trans, pBP, out, osz);
    {
        size_t total = (size_t)LL * BB * HID / 4;
        feat_out_k<<<(unsigned)((total + 255) / 256), 256>>>(x, out, osz);
    }
    mask_out_k<<<(BB * LL + 255) / 256, 256>>>(out, osz);
}